// round 3
// baseline (speedup 1.0000x reference)
#include <cuda_runtime.h>
#include <math.h>

#define NTOK 4096
#define NELEM (NTOK*96)
#define SCALE_F 0.35355339059327373f
#define NEG_INF (-3.402823466e38f)

__device__ float g_qkv[9][2][8*NTOK];   // [type 0..8: camq,camk,camv,pamq,...,chamv]
__device__ float g_ycam[2][8*NTOK];
__device__ float g_ypam[2][8*NTOK];     // flat n*8+c (raw reshape)
__device__ float g_ycham[2][8*NTOK];
__device__ float g_ycwam[2][NELEM];

struct QKVParams { const float* w[9]; const float* bia[9]; };
struct EpiParams { const float* pw[4]; const float* g[4]; const float* gamma[4]; };

// -------- fused qkv conv1x1: 9 outputs of shape (8,4096) per batch --------
__global__ void __launch_bounds__(256) qkv_kernel(const float* __restrict__ x, QKVParams P) {
    __shared__ float sw[72*100];
    __shared__ float sb[72];
    const int b = blockIdx.y, n0 = blockIdx.x*128, t = threadIdx.x;
    for (int i = t; i < 72*96; i += 256) {
        int o = i/96, c = i - o*96;                 // o = og*9+kk
        sw[o*100+c] = __ldg(P.w[o%9] + (o/9)*96 + c);
    }
    if (t < 72) sb[t] = __ldg(P.bia[t%9] + t/9);
    __syncthreads();
    const int og = t & 7, nl = t >> 3;
    const float* xb = x + b*NELEM + n0 + nl;
    float acc[9][4];
#pragma unroll
    for (int kk = 0; kk < 9; kk++) {
        float bb = sb[og*9+kk];
#pragma unroll
        for (int j = 0; j < 4; j++) acc[kk][j] = bb;
    }
    for (int c = 0; c < 96; c++) {
        float xv[4];
#pragma unroll
        for (int j = 0; j < 4; j++) xv[j] = __ldg(xb + c*NTOK + 32*j);
#pragma unroll
        for (int kk = 0; kk < 9; kk++) {
            float wv = sw[(og*9+kk)*100 + c];
#pragma unroll
            for (int j = 0; j < 4; j++) acc[kk][j] += wv*xv[j];
        }
    }
#pragma unroll
    for (int kk = 0; kk < 9; kk++)
#pragma unroll
        for (int j = 0; j < 4; j++)
            g_qkv[kk][b][og*NTOK + n0 + nl + 32*j] = acc[kk][j];
}

// -------- CAM: 8x8 attention over n=4096 --------
__global__ void __launch_bounds__(256) cam_kernel() {
    const int b = blockIdx.x, slice = blockIdx.y;
    const float *q = g_qkv[0][b], *k = g_qkv[1][b], *v = g_qkv[2][b];
    __shared__ float sp[8][8];
    const int w = threadIdx.x >> 5, lane = threadIdx.x & 31;
    float acc[8] = {};
    for (int i = lane; i < NTOK; i += 32) {
        float qv = q[w*NTOK+i];
#pragma unroll
        for (int d = 0; d < 8; d++) acc[d] += qv*k[d*NTOK+i];
    }
#pragma unroll
    for (int d = 0; d < 8; d++)
#pragma unroll
        for (int off = 16; off; off >>= 1)
            acc[d] += __shfl_xor_sync(0xffffffffu, acc[d], off);
    if (lane == 0) {
        float mx = NEG_INF, s = 0.f, e[8];
#pragma unroll
        for (int d = 0; d < 8; d++) mx = fmaxf(mx, acc[d]*SCALE_F);
#pragma unroll
        for (int d = 0; d < 8; d++) { e[d] = __expf(acc[d]*SCALE_F - mx); s += e[d]; }
#pragma unroll
        for (int d = 0; d < 8; d++) sp[w][d] = e[d]/s;
    }
    __syncthreads();
    for (int idx = threadIdx.x; idx < 4096; idx += 256) {
        int c = idx >> 9, n = slice*512 + (idx & 511);
        float a0 = 0.f;
#pragma unroll
        for (int d = 0; d < 8; d++) a0 += sp[c][d]*v[d*NTOK+n];
        g_ycam[b][c*NTOK+n] = a0;
    }
}

// -------- PAM: flash attention 4096x4096, d=8; 64 rows/CTA, 4-way m split --------
__global__ void __launch_bounds__(256) pam_kernel() {
    const int a0 = blockIdx.x*64, b = blockIdx.y;
    const float *q = g_qkv[3][b], *k = g_qkv[4][b], *v = g_qkv[5][b];
    __shared__ float kt[512][8], vt[512][8];
    __shared__ float rm[64][4], rl[64][4], ry[64][4][8];
    const int a = threadIdx.x >> 2, p = threadIdx.x & 3;
    float qr[8];
#pragma unroll
    for (int c = 0; c < 8; c++) qr[c] = q[c*NTOK + a0 + a]*SCALE_F;
    float mx = NEG_INF, l = 0.f, y[8] = {};
    for (int m0 = 0; m0 < NTOK; m0 += 512) {
        __syncthreads();
        for (int i = threadIdx.x; i < 4096; i += 256) {
            int c = i >> 9, m = i & 511;
            kt[m][c] = k[c*NTOK + m0 + m];
            vt[m][c] = v[c*NTOK + m0 + m];
        }
        __syncthreads();
        for (int mi = p; mi < 512; mi += 4) {
            float4 k0 = *(const float4*)&kt[mi][0], k1 = *(const float4*)&kt[mi][4];
            float s = qr[0]*k0.x+qr[1]*k0.y+qr[2]*k0.z+qr[3]*k0.w
                    + qr[4]*k1.x+qr[5]*k1.y+qr[6]*k1.z+qr[7]*k1.w;
            float mn = fmaxf(mx, s), corr = __expf(mx - mn), pe = __expf(s - mn);
            mx = mn; l = l*corr + pe;
            float4 v0 = *(const float4*)&vt[mi][0], v1 = *(const float4*)&vt[mi][4];
            y[0]=y[0]*corr+pe*v0.x; y[1]=y[1]*corr+pe*v0.y; y[2]=y[2]*corr+pe*v0.z; y[3]=y[3]*corr+pe*v0.w;
            y[4]=y[4]*corr+pe*v1.x; y[5]=y[5]*corr+pe*v1.y; y[6]=y[6]*corr+pe*v1.z; y[7]=y[7]*corr+pe*v1.w;
        }
    }
    rm[a][p] = mx; rl[a][p] = l;
#pragma unroll
    for (int c = 0; c < 8; c++) ry[a][p][c] = y[c];
    __syncthreads();
    if (p == 0) {
        float M = rm[a][0];
#pragma unroll
        for (int pp = 1; pp < 4; pp++) M = fmaxf(M, rm[a][pp]);
        float L = 0.f, Y[8] = {};
#pragma unroll
        for (int pp = 0; pp < 4; pp++) {
            float f = __expf(rm[a][pp] - M);
            L += rl[a][pp]*f;
#pragma unroll
            for (int c = 0; c < 8; c++) Y[c] += ry[a][pp][c]*f;
        }
#pragma unroll
        for (int c = 0; c < 8; c++) g_ypam[b][(a0+a)*8 + c] = Y[c]/L;
    }
}

// -------- CHAM: 512x512 attention, d=64; 16 rows/CTA --------
__global__ void __launch_bounds__(256) cham_kernel() {
    const int a0 = blockIdx.x*16, b = blockIdx.y;
    const float *q = g_qkv[6][b], *k = g_qkv[7][b], *v = g_qkv[8][b];
    __shared__ float sq[16*68];
    __shared__ float ss[16*516];
    const int t = threadIdx.x;
    for (int i = t; i < 1024; i += 256)
        sq[(i>>6)*68 + (i&63)] = q[(a0 + (i>>6))*64 + (i&63)]*SCALE_F;
    __syncthreads();
    const int a = t >> 4, lc = t & 15;
    for (int j = 0; j < 32; j++) {
        int c = lc + 16*j;
        const float* kr = k + c*64;
        float s = 0.f;
#pragma unroll
        for (int i = 0; i < 64; i += 4) {
            float4 qv = *(const float4*)(sq + a*68 + i);
            float4 kv = __ldg((const float4*)(kr + i));
            s += qv.x*kv.x + qv.y*kv.y + qv.z*kv.z + qv.w*kv.w;
        }
        ss[a*516+c] = s;
    }
    __syncthreads();
    float vals[32], M = NEG_INF;
#pragma unroll
    for (int j = 0; j < 32; j++) { vals[j] = ss[a*516 + lc + 16*j]; M = fmaxf(M, vals[j]); }
#pragma unroll
    for (int off = 8; off; off >>= 1) M = fmaxf(M, __shfl_xor_sync(0xffffffffu, M, off));
    float S = 0.f;
#pragma unroll
    for (int j = 0; j < 32; j++) { vals[j] = __expf(vals[j] - M); S += vals[j]; }
#pragma unroll
    for (int off = 8; off; off >>= 1) S += __shfl_xor_sync(0xffffffffu, S, off);
    float inv = 1.f/S;
#pragma unroll
    for (int j = 0; j < 32; j++) ss[a*516 + lc + 16*j] = vals[j]*inv;
    __syncthreads();
    const int w0 = lc*4;
    float4 acc = make_float4(0.f, 0.f, 0.f, 0.f);
    for (int c = 0; c < 512; c++) {
        float pv = ss[a*516+c];
        float4 vv = __ldg((const float4*)(v + c*64 + w0));
        acc.x += pv*vv.x; acc.y += pv*vv.y; acc.z += pv*vv.z; acc.w += pv*vv.w;
    }
    *(float4*)(g_ycham[b] + (a0+a)*64 + w0) = acc;
}

// -------- CWAM: flash attention 6144x6144, d=64; q=k=v = raw rows of x --------
// 32 rows/CTA; thread(ty,tx): rows {2ty,2ty+1}; score cols {tx+16j}; y cols {4tx..4tx+3}
__global__ void __launch_bounds__(256) cwam_kernel(const float* __restrict__ x) {
    __shared__ float qs[32*68], kt[64*68], ps[32*68];
    const int b = blockIdx.y, a0 = blockIdx.x*32, t = threadIdx.x;
    const int ty = t >> 4, tx = t & 15, r0 = ty*2;
    const float* xb = x + b*NELEM;
    for (int i = t; i < 512; i += 256) {
        float4 v4 = __ldg((const float4*)(xb + a0*64) + i);
        int e = i*4;
        *(float4*)(qs + (e>>6)*68 + (e&63)) =
            make_float4(v4.x*SCALE_F, v4.y*SCALE_F, v4.z*SCALE_F, v4.w*SCALE_F);
    }
    float m[2] = {NEG_INF, NEG_INF}, l[2] = {0.f, 0.f}, y[2][4] = {};
    for (int c0 = 0; c0 < 6144; c0 += 64) {
        __syncthreads();
        for (int i = t; i < 1024; i += 256) {
            float4 v4 = __ldg((const float4*)(xb + c0*64) + i);
            int e = i*4;
            *(float4*)(kt + (e>>6)*68 + (e&63)) = v4;
        }
        __syncthreads();
        float s[2][4] = {};
#pragma unroll
        for (int hb = 0; hb < 64; hb += 4) {
            float4 k4[4];
#pragma unroll
            for (int j = 0; j < 4; j++) k4[j] = *(const float4*)(kt + (tx+16*j)*68 + hb);
#pragma unroll
            for (int r = 0; r < 2; r++) {
                float4 q4 = *(const float4*)(qs + (r0+r)*68 + hb);
#pragma unroll
                for (int j = 0; j < 4; j++)
                    s[r][j] += q4.x*k4[j].x + q4.y*k4[j].y + q4.z*k4[j].z + q4.w*k4[j].w;
            }
        }
        float corr[2];
#pragma unroll
        for (int r = 0; r < 2; r++) {
            float mt = fmaxf(fmaxf(s[r][0], s[r][1]), fmaxf(s[r][2], s[r][3]));
#pragma unroll
            for (int off = 8; off; off >>= 1) mt = fmaxf(mt, __shfl_xor_sync(0xffffffffu, mt, off));
            float mn = fmaxf(m[r], mt);
            corr[r] = __expf(m[r] - mn); m[r] = mn;
            float ls = 0.f;
#pragma unroll
            for (int j = 0; j < 4; j++) { s[r][j] = __expf(s[r][j] - mn); ls += s[r][j]; }
#pragma unroll
            for (int off = 8; off; off >>= 1) ls += __shfl_xor_sync(0xffffffffu, ls, off);
            l[r] = l[r]*corr[r] + ls;
#pragma unroll
            for (int j = 0; j < 4; j++) {
                y[r][j] *= corr[r];
                ps[(r0+r)*68 + tx + 16*j] = s[r][j];
            }
        }
        __syncthreads();
        for (int c = 0; c < 64; c++) {
            float p0 = ps[r0*68 + c], p1 = ps[(r0+1)*68 + c];
            float4 vv = *(const float4*)(kt + c*68 + 4*tx);
            y[0][0] += p0*vv.x; y[0][1] += p0*vv.y; y[0][2] += p0*vv.z; y[0][3] += p0*vv.w;
            y[1][0] += p1*vv.x; y[1][1] += p1*vv.y; y[1][2] += p1*vv.z; y[1][3] += p1*vv.w;
        }
    }
#pragma unroll
    for (int r = 0; r < 2; r++) {
        float inv = 1.f/l[r];
        float4 o4 = make_float4(y[r][0]*inv, y[r][1]*inv, y[r][2]*inv, y[r][3]*inv);
        *(float4*)(g_ycwam[b] + (a0+r0+r)*64 + 4*tx) = o4;
    }
}

// -------- epilogue: 4x grouped conv3x3 + exact GELU + gamma*(1+g) combine --------
__global__ void __launch_bounds__(256) epi_kernel(float* __restrict__ out, EpiParams E) {
    const int b = blockIdx.y, o = blockIdx.x;   // output channel 0..95
    __shared__ float w[4][9];
    __shared__ float gg[4];
    if (threadIdx.x < 36)
        w[threadIdx.x/9][threadIdx.x%9] = __ldg(E.pw[threadIdx.x/9] + o*9 + threadIdx.x%9);
    if (threadIdx.x < 4)
        gg[threadIdx.x] = __ldg(E.gamma[threadIdx.x]) * (1.f + __ldg(E.g[threadIdx.x]));
    __syncthreads();
    const int g8 = o/12;
    const float* inp[4] = { g_ycam[b] + g8*4096, g_ypam[b] + g8*4096,
                            g_ycham[b] + g8*4096, g_ycwam[b] + o*4096 };
    for (int pix = threadIdx.x; pix < 4096; pix += 256) {
        int h = pix >> 6, wx = pix & 63;
        float acc = 0.f;
#pragma unroll
        for (int br = 0; br < 4; br++) {
            float c = 0.f;
#pragma unroll
            for (int dy = -1; dy <= 1; dy++)
#pragma unroll
                for (int dx = -1; dx <= 1; dx++) {
                    int hh = h + dy, ww = wx + dx;
                    float v = (hh >= 0 && hh < 64 && ww >= 0 && ww < 64)
                              ? __ldg(inp[br] + hh*64 + ww) : 0.f;
                    c += w[br][(dy+1)*3 + dx + 1] * v;
                }
            float ge = 0.5f*c*(1.f + erff(c*0.70710678118654752f));
            acc += gg[br]*ge;
        }
        out[b*NELEM + pix*96 + o] = acc;
    }
}

extern "C" void kernel_launch(void* const* d_in, const int* in_sizes, int n_in,
                              void* d_out, int out_size) {
    const float* x = (const float*)d_in[0];
    // order: x, cam(qw qb kw kb vw vb pw g), pam(...), cham(...), cwam_pw, cwam_g, gamma1..4
    static const int wi[9] = {1,3,5, 9,11,13, 17,19,21};
    QKVParams P;
    for (int i = 0; i < 9; i++) {
        P.w[i]   = (const float*)d_in[wi[i]];
        P.bia[i] = (const float*)d_in[wi[i]+1];
    }
    static const int pi[4] = {7,15,23,25};
    EpiParams E;
    for (int i = 0; i < 4; i++) {
        E.pw[i]    = (const float*)d_in[pi[i]];
        E.g[i]     = (const float*)d_in[pi[i]+1];
        E.gamma[i] = (const float*)d_in[27+i];
    }
    float* out = (float*)d_out;
    qkv_kernel <<<dim3(32,2),  256>>>(x, P);
    cam_kernel <<<dim3(2,8),   256>>>();
    pam_kernel <<<dim3(64,2),  256>>>();
    cham_kernel<<<dim3(32,2),  256>>>();
    cwam_kernel<<<dim3(192,2), 256>>>(x);
    epi_kernel <<<dim3(96,2),  256>>>(out, E);
}

// round 6
// speedup vs baseline: 2.7507x; 2.7507x over previous
#include <cuda_runtime.h>
#include <cuda_bf16.h>
#include <math.h>
#include <stdint.h>

#define NTOK 4096
#define NELEM (NTOK*96)
#define SCALE_F 0.35355339059327373f
#define NEG_INF (-3.402823466e38f)

__device__ float g_qkv[9][2][8*NTOK];
__device__ float g_ycam[2][8*NTOK];
__device__ float g_ypam[2][8*NTOK];
__device__ float g_ycham[2][8*NTOK];
__device__ float g_ycwam[2][NELEM];

struct QKVParams { const float* w[9]; const float* bia[9]; };
struct EpiParams { const float* pw[4]; const float* g[4]; const float* gamma[4]; };

// ---- fast exp on the FMA pipe (no MUFU) ----
__device__ __forceinline__ float fexp(float x) {
    x = fmaxf(x, -80.f);
    float t = fmaf(x, 1.4426950408889634f, 12582912.f);
    float e = t - 12582912.f;
    float f = fmaf(x, 1.4426950408889634f, -e);
    float p = 1.5403530e-4f;
    p = fmaf(p, f, 1.3333558e-3f);
    p = fmaf(p, f, 9.6181291e-3f);
    p = fmaf(p, f, 5.5504109e-2f);
    p = fmaf(p, f, 2.4022651e-1f);
    p = fmaf(p, f, 6.9314718e-1f);
    p = fmaf(p, f, 1.0f);
    return p * __int_as_float(((int)e + 127) << 23);
}

__device__ __forceinline__ uint32_t bfpack(float a, float b) {
    return ((uint32_t)__bfloat16_as_ushort(__float2bfloat16_rn(b)) << 16)
         |  (uint32_t)__bfloat16_as_ushort(__float2bfloat16_rn(a));
}
__device__ __forceinline__ float bfhi(float a) {
    return __bfloat162float(__float2bfloat16_rn(a));
}
__device__ __forceinline__ uint16_t bfu16(float a) {
    return __bfloat16_as_ushort(__float2bfloat16_rn(a));
}

#define MMA16(d, a, b0, b1) asm volatile( \
    "mma.sync.aligned.m16n8k16.row.col.f32.bf16.bf16.f32 " \
    "{%0,%1,%2,%3},{%4,%5,%6,%7},{%8,%9},{%0,%1,%2,%3};" \
    : "+f"((d)[0]),"+f"((d)[1]),"+f"((d)[2]),"+f"((d)[3]) \
    : "r"((a)[0]),"r"((a)[1]),"r"((a)[2]),"r"((a)[3]), "r"(b0),"r"(b1))

// smem layout in u32 units
#define KHI_O   0            /* 128 tok * 36 u32 */
#define KLO_O   4608
#define VTH_O   9216         /* 64 tokpair * 72 u32: [tp][dim] packed tok pairs */
#define VTL_O   13824
#define CWAM_SMEM (18432*4)  /* 73728 B */

// ======== CWAM: flash attention 6144x6144, d=64, q=k=v = raw rows of x ========
// CTA: 64 q-rows, 128 threads (4 warps x 16 rows). bf16 hi/lo split MMAs.
__global__ void __launch_bounds__(128) cwam_mma(const float* __restrict__ x) {
    extern __shared__ uint32_t sm[];
    uint32_t* khi = sm + KHI_O;
    uint32_t* klo = sm + KLO_O;
    uint32_t* vth = sm + VTH_O;
    uint32_t* vtl = sm + VTL_O;
    const int b = blockIdx.y, a0 = blockIdx.x*64, t = threadIdx.x;
    const int w = t >> 5, lane = t & 31, g = lane >> 2, q = lane & 3;
    const float* xb = x + b*NELEM;
    // ---- preload Q fragments (rows a0 + w*16 + g, +8), SCALE folded ----
    uint32_t qhi[4][4], qlo[4][4];
    const int r0 = a0 + w*16 + g;
#pragma unroll
    for (int ks = 0; ks < 4; ks++)
#pragma unroll
        for (int half = 0; half < 2; half++)
#pragma unroll
            for (int rr = 0; rr < 2; rr++) {
                int row = r0 + rr*8;
                int col = ks*16 + half*8 + 2*q;
                float2 v = *(const float2*)(xb + row*64 + col);
                v.x *= SCALE_F; v.y *= SCALE_F;
                float hx = bfhi(v.x), hy = bfhi(v.y);
                qhi[ks][half*2+rr] = bfpack(hx, hy);
                qlo[ks][half*2+rr] = bfpack(v.x - hx, v.y - hy);
            }
    float m0 = NEG_INF, m1 = NEG_INF, l0 = 0.f, l1 = 0.f;
    float Y[8][4];
#pragma unroll
    for (int i = 0; i < 8; i++) { Y[i][0]=0.f; Y[i][1]=0.f; Y[i][2]=0.f; Y[i][3]=0.f; }

    for (int c0 = 0; c0 < 6144; c0 += 128) {
        __syncthreads();
        // ---- load 128 tokens x 64 dims; K hi/lo [tok][36] + Vt hi/lo [tokpair][72] ----
        const float4* src = (const float4*)(xb + c0*64);
        uint16_t* vh16 = (uint16_t*)vth;
        uint16_t* vl16 = (uint16_t*)vtl;
#pragma unroll
        for (int i = 0; i < 16; i++) {
            int idx = i*128 + t;               // coalesced float4 index
            float4 v = __ldg(src + idx);
            int tok = idx >> 4, d0 = (idx & 15) * 4;
            float hx=bfhi(v.x), hy=bfhi(v.y), hz=bfhi(v.z), hw=bfhi(v.w);
            khi[tok*36 + d0/2    ] = bfpack(hx, hy);
            khi[tok*36 + d0/2 + 1] = bfpack(hz, hw);
            klo[tok*36 + d0/2    ] = bfpack(v.x-hx, v.y-hy);
            klo[tok*36 + d0/2 + 1] = bfpack(v.z-hz, v.w-hw);
            int tp = tok >> 1, lo = tok & 1;   // u16 idx = tp*144 + dim*2 + lo
            int u0 = tp*144 + d0*2 + lo;
            vh16[u0    ] = bfu16(v.x);
            vh16[u0 + 2] = bfu16(v.y);
            vh16[u0 + 4] = bfu16(v.z);
            vh16[u0 + 6] = bfu16(v.w);
            vl16[u0    ] = bfu16(v.x-hx);
            vl16[u0 + 2] = bfu16(v.y-hy);
            vl16[u0 + 4] = bfu16(v.z-hz);
            vl16[u0 + 6] = bfu16(v.w-hw);
        }
        __syncthreads();
        // ---- S = Q K^T (16 x 128 per warp), hi/lo 3-combo ----
        float d[16][4];
#pragma unroll
        for (int ns = 0; ns < 16; ns++) { d[ns][0]=0.f; d[ns][1]=0.f; d[ns][2]=0.f; d[ns][3]=0.f; }
#pragma unroll
        for (int ks = 0; ks < 4; ks++)
#pragma unroll
            for (int ns = 0; ns < 16; ns++) {
                int tok = ns*8 + g;
                uint32_t bh0 = khi[tok*36 + ks*8 + q];
                uint32_t bh1 = khi[tok*36 + ks*8 + 4 + q];
                uint32_t bl0 = klo[tok*36 + ks*8 + q];
                uint32_t bl1 = klo[tok*36 + ks*8 + 4 + q];
                MMA16(d[ns], qhi[ks], bh0, bh1);
                MMA16(d[ns], qhi[ks], bl0, bl1);
                MMA16(d[ns], qlo[ks], bh0, bh1);
            }
        // ---- online softmax (rows r0 and r0+8) ----
        float mt0 = NEG_INF, mt1 = NEG_INF;
#pragma unroll
        for (int ns = 0; ns < 16; ns++) {
            mt0 = fmaxf(mt0, fmaxf(d[ns][0], d[ns][1]));
            mt1 = fmaxf(mt1, fmaxf(d[ns][2], d[ns][3]));
        }
#pragma unroll
        for (int off = 1; off <= 2; off <<= 1) {
            mt0 = fmaxf(mt0, __shfl_xor_sync(0xffffffffu, mt0, off));
            mt1 = fmaxf(mt1, __shfl_xor_sync(0xffffffffu, mt1, off));
        }
        float mn0 = fmaxf(m0, mt0), mn1 = fmaxf(m1, mt1);
        float cr0 = fexp(m0 - mn0), cr1 = fexp(m1 - mn1);
        m0 = mn0; m1 = mn1;
        float s0 = 0.f, s1 = 0.f;
#pragma unroll
        for (int ns = 0; ns < 16; ns++) {
            d[ns][0] = fexp(d[ns][0] - mn0); d[ns][1] = fexp(d[ns][1] - mn0);
            d[ns][2] = fexp(d[ns][2] - mn1); d[ns][3] = fexp(d[ns][3] - mn1);
            s0 += d[ns][0] + d[ns][1];
            s1 += d[ns][2] + d[ns][3];
        }
#pragma unroll
        for (int off = 1; off <= 2; off <<= 1) {
            s0 += __shfl_xor_sync(0xffffffffu, s0, off);
            s1 += __shfl_xor_sync(0xffffffffu, s1, off);
        }
        l0 = l0*cr0 + s0; l1 = l1*cr1 + s1;
#pragma unroll
        for (int nd = 0; nd < 8; nd++) {
            Y[nd][0] *= cr0; Y[nd][1] *= cr0; Y[nd][2] *= cr1; Y[nd][3] *= cr1;
        }
        // ---- Y += P V (P from d frags, hi/lo split) ----
#pragma unroll
        for (int ks2 = 0; ks2 < 8; ks2++) {
            uint32_t ah[4], al[4];
            float p00 = d[2*ks2][0],   p01 = d[2*ks2][1];
            float p02 = d[2*ks2][2],   p03 = d[2*ks2][3];
            float p10 = d[2*ks2+1][0], p11 = d[2*ks2+1][1];
            float p12 = d[2*ks2+1][2], p13 = d[2*ks2+1][3];
            float h0 = bfhi(p00), h1 = bfhi(p01);
            ah[0] = bfpack(h0, h1); al[0] = bfpack(p00-h0, p01-h1);
            h0 = bfhi(p02); h1 = bfhi(p03);
            ah[1] = bfpack(h0, h1); al[1] = bfpack(p02-h0, p03-h1);
            h0 = bfhi(p10); h1 = bfhi(p11);
            ah[2] = bfpack(h0, h1); al[2] = bfpack(p10-h0, p11-h1);
            h0 = bfhi(p12); h1 = bfhi(p13);
            ah[3] = bfpack(h0, h1); al[3] = bfpack(p12-h0, p13-h1);
#pragma unroll
            for (int nd = 0; nd < 8; nd++) {
                int dim = nd*8 + g;
                uint32_t bh0 = vth[(ks2*8 + q)*72 + dim];
                uint32_t bh1 = vth[(ks2*8 + 4 + q)*72 + dim];
                uint32_t bl0 = vtl[(ks2*8 + q)*72 + dim];
                uint32_t bl1 = vtl[(ks2*8 + 4 + q)*72 + dim];
                MMA16(Y[nd], ah, bh0, bh1);
                MMA16(Y[nd], al, bh0, bh1);
                MMA16(Y[nd], ah, bl0, bl1);
            }
        }
    }
    float i0 = 1.f/l0, i1 = 1.f/l1;
    float* yb = g_ycwam[b];
#pragma unroll
    for (int nd = 0; nd < 8; nd++) {
        int col = nd*8 + 2*q;
        *(float2*)(yb + r0*64 + col)     = make_float2(Y[nd][0]*i0, Y[nd][1]*i0);
        *(float2*)(yb + (r0+8)*64 + col) = make_float2(Y[nd][2]*i1, Y[nd][3]*i1);
    }
}

// ======== fused qkv conv1x1 ========
__global__ void __launch_bounds__(256) qkv_kernel(const float* __restrict__ x, QKVParams P) {
    __shared__ float sw[72*100];
    __shared__ float sb[72];
    const int b = blockIdx.y, n0 = blockIdx.x*128, t = threadIdx.x;
    for (int i = t; i < 72*96; i += 256) {
        int o = i/96, c = i - o*96;
        sw[o*100+c] = __ldg(P.w[o%9] + (o/9)*96 + c);
    }
    if (t < 72) sb[t] = __ldg(P.bia[t%9] + t/9);
    __syncthreads();
    const int og = t & 7, nl = t >> 3;
    const float* xb = x + b*NELEM + n0 + nl;
    float acc[9][4];
#pragma unroll
    for (int kk = 0; kk < 9; kk++) {
        float bb = sb[og*9+kk];
#pragma unroll
        for (int j = 0; j < 4; j++) acc[kk][j] = bb;
    }
    for (int c = 0; c < 96; c++) {
        float xv[4];
#pragma unroll
        for (int j = 0; j < 4; j++) xv[j] = __ldg(xb + c*NTOK + 32*j);
#pragma unroll
        for (int kk = 0; kk < 9; kk++) {
            float wv = sw[(og*9+kk)*100 + c];
#pragma unroll
            for (int j = 0; j < 4; j++) acc[kk][j] += wv*xv[j];
        }
    }
#pragma unroll
    for (int kk = 0; kk < 9; kk++)
#pragma unroll
        for (int j = 0; j < 4; j++)
            g_qkv[kk][b][og*NTOK + n0 + nl + 32*j] = acc[kk][j];
}

// ======== CAM ========
__global__ void __launch_bounds__(256) cam_kernel() {
    const int b = blockIdx.x, slice = blockIdx.y;
    const float *q = g_qkv[0][b], *k = g_qkv[1][b], *v = g_qkv[2][b];
    __shared__ float sp[8][8];
    const int w = threadIdx.x >> 5, lane = threadIdx.x & 31;
    float acc[8] = {};
    for (int i = lane; i < NTOK; i += 32) {
        float qv = q[w*NTOK+i];
#pragma unroll
        for (int d = 0; d < 8; d++) acc[d] += qv*k[d*NTOK+i];
    }
#pragma unroll
    for (int d = 0; d < 8; d++)
#pragma unroll
        for (int off = 16; off; off >>= 1)
            acc[d] += __shfl_xor_sync(0xffffffffu, acc[d], off);
    if (lane == 0) {
        float mx = NEG_INF, s = 0.f, e[8];
#pragma unroll
        for (int d = 0; d < 8; d++) mx = fmaxf(mx, acc[d]*SCALE_F);
#pragma unroll
        for (int d = 0; d < 8; d++) { e[d] = fexp(acc[d]*SCALE_F - mx); s += e[d]; }
#pragma unroll
        for (int d = 0; d < 8; d++) sp[w][d] = e[d]/s;
    }
    __syncthreads();
    for (int idx = threadIdx.x; idx < 4096; idx += 256) {
        int c = idx >> 9, n = slice*512 + (idx & 511);
        float a0 = 0.f;
#pragma unroll
        for (int d = 0; d < 8; d++) a0 += sp[c][d]*v[d*NTOK+n];
        g_ycam[b][c*NTOK+n] = a0;
    }
}

// ======== PAM flash (4096x4096, d=8) ========
__global__ void __launch_bounds__(256) pam_kernel() {
    const int a0 = blockIdx.x*64, b = blockIdx.y;
    const float *q = g_qkv[3][b], *k = g_qkv[4][b], *v = g_qkv[5][b];
    __shared__ float kt[512][8], vt[512][8];
    __shared__ float rm[64][4], rl[64][4], ry[64][4][8];
    const int a = threadIdx.x >> 2, p = threadIdx.x & 3;
    float qr[8];
#pragma unroll
    for (int c = 0; c < 8; c++) qr[c] = q[c*NTOK + a0 + a]*SCALE_F;
    float mx = NEG_INF, l = 0.f, y[8] = {};
    for (int m0 = 0; m0 < NTOK; m0 += 512) {
        __syncthreads();
        for (int i = threadIdx.x; i < 4096; i += 256) {
            int c = i >> 9, mm = i & 511;
            kt[mm][c] = k[c*NTOK + m0 + mm];
            vt[mm][c] = v[c*NTOK + m0 + mm];
        }
        __syncthreads();
        for (int mi = p; mi < 512; mi += 4) {
            float4 k0 = *(const float4*)&kt[mi][0], k1 = *(const float4*)&kt[mi][4];
            float s = qr[0]*k0.x+qr[1]*k0.y+qr[2]*k0.z+qr[3]*k0.w
                    + qr[4]*k1.x+qr[5]*k1.y+qr[6]*k1.z+qr[7]*k1.w;
            float mn = fmaxf(mx, s), corr = fexp(mx - mn), pe = fexp(s - mn);
            mx = mn; l = l*corr + pe;
            float4 v0 = *(const float4*)&vt[mi][0], v1 = *(const float4*)&vt[mi][4];
            y[0]=y[0]*corr+pe*v0.x; y[1]=y[1]*corr+pe*v0.y; y[2]=y[2]*corr+pe*v0.z; y[3]=y[3]*corr+pe*v0.w;
            y[4]=y[4]*corr+pe*v1.x; y[5]=y[5]*corr+pe*v1.y; y[6]=y[6]*corr+pe*v1.z; y[7]=y[7]*corr+pe*v1.w;
        }
    }
    rm[a][p] = mx; rl[a][p] = l;
#pragma unroll
    for (int c = 0; c < 8; c++) ry[a][p][c] = y[c];
    __syncthreads();
    if (p == 0) {
        float M = rm[a][0];
#pragma unroll
        for (int pp = 1; pp < 4; pp++) M = fmaxf(M, rm[a][pp]);
        float L = 0.f, Yv[8] = {};
#pragma unroll
        for (int pp = 0; pp < 4; pp++) {
            float f = fexp(rm[a][pp] - M);
            L += rl[a][pp]*f;
#pragma unroll
            for (int c = 0; c < 8; c++) Yv[c] += ry[a][pp][c]*f;
        }
#pragma unroll
        for (int c = 0; c < 8; c++) g_ypam[b][(a0+a)*8 + c] = Yv[c]/L;
    }
}

// ======== CHAM: 512x512, d=64; 4 rows/CTA ========
__global__ void __launch_bounds__(256) cham_kernel() {
    const int a0 = blockIdx.x*4, b = blockIdx.y;
    const float *q = g_qkv[6][b], *k = g_qkv[7][b], *v = g_qkv[8][b];
    __shared__ float sq[4][64];
    __shared__ float ss[4][512];
    __shared__ float redM[4][2], redS[4][2];
    const int t = threadIdx.x, a = t >> 6, ln = t & 63;
    sq[a][ln] = q[(a0+a)*64 + ln]*SCALE_F;
    __syncthreads();
    float vals[8];
#pragma unroll 2
    for (int j = 0; j < 8; j++) {
        int c = ln + 64*j;
        const float4* kr = (const float4*)(k + c*64);
        const float4* qr = (const float4*)sq[a];
        float s = 0.f;
#pragma unroll
        for (int i = 0; i < 16; i++) {
            float4 qv = qr[i], kv = __ldg(kr + i);
            s += qv.x*kv.x + qv.y*kv.y + qv.z*kv.z + qv.w*kv.w;
        }
        vals[j] = s;
    }
    float M = vals[0];
#pragma unroll
    for (int j = 1; j < 8; j++) M = fmaxf(M, vals[j]);
#pragma unroll
    for (int off = 16; off; off >>= 1) M = fmaxf(M, __shfl_xor_sync(0xffffffffu, M, off));
    if ((t & 31) == 0) redM[a][ln >> 5] = M;
    __syncthreads();
    M = fmaxf(redM[a][0], redM[a][1]);
    float S = 0.f;
#pragma unroll
    for (int j = 0; j < 8; j++) { vals[j] = fexp(vals[j] - M); S += vals[j]; }
#pragma unroll
    for (int off = 16; off; off >>= 1) S += __shfl_xor_sync(0xffffffffu, S, off);
    if ((t & 31) == 0) redS[a][ln >> 5] = S;
    __syncthreads();
    float inv = 1.f / (redS[a][0] + redS[a][1]);
#pragma unroll
    for (int j = 0; j < 8; j++) ss[a][ln + 64*j] = vals[j]*inv;
    __syncthreads();
    const float* vc = v + ln;
    float c0 = 0.f, c1 = 0.f, c2 = 0.f, c3 = 0.f;
    for (int c = 0; c < 512; c += 4) {
        c0 += ss[a][c  ]*__ldg(vc + (c  )*64);
        c1 += ss[a][c+1]*__ldg(vc + (c+1)*64);
        c2 += ss[a][c+2]*__ldg(vc + (c+2)*64);
        c3 += ss[a][c+3]*__ldg(vc + (c+3)*64);
    }
    g_ycham[b][(a0+a)*64 + ln] = (c0 + c1) + (c2 + c3);
}

// ======== epilogue ========
__global__ void __launch_bounds__(256) epi_kernel(float* __restrict__ out, EpiParams E) {
    const int b = blockIdx.y, o = blockIdx.x;
    __shared__ float w[4][9];
    __shared__ float gg[4];
    if (threadIdx.x < 36)
        w[threadIdx.x/9][threadIdx.x%9] = __ldg(E.pw[threadIdx.x/9] + o*9 + threadIdx.x%9);
    if (threadIdx.x < 4)
        gg[threadIdx.x] = __ldg(E.gamma[threadIdx.x]) * (1.f + __ldg(E.g[threadIdx.x]));
    __syncthreads();
    const int g8 = o/12;
    const float* inp[4] = { g_ycam[b] + g8*4096, g_ypam[b] + g8*4096,
                            g_ycham[b] + g8*4096, g_ycwam[b] + o*4096 };
    for (int pix = threadIdx.x; pix < 4096; pix += 256) {
        int h = pix >> 6, wx = pix & 63;
        float acc = 0.f;
#pragma unroll
        for (int br = 0; br < 4; br++) {
            float c = 0.f;
#pragma unroll
            for (int dy = -1; dy <= 1; dy++)
#pragma unroll
                for (int dx = -1; dx <= 1; dx++) {
                    int hh2 = h + dy, ww = wx + dx;
                    float vv = (hh2 >= 0 && hh2 < 64 && ww >= 0 && ww < 64)
                               ? __ldg(inp[br] + hh2*64 + ww) : 0.f;
                    c += w[br][(dy+1)*3 + dx + 1] * vv;
                }
            float ge = 0.5f*c*(1.f + erff(c*0.70710678118654752f));
            acc += gg[br]*ge;
        }
        out[b*NELEM + pix*96 + o] = acc;
    }
}

extern "C" void kernel_launch(void* const* d_in, const int* in_sizes, int n_in,
                              void* d_out, int out_size) {
    const float* x = (const float*)d_in[0];
    static const int wi[9] = {1,3,5, 9,11,13, 17,19,21};
    QKVParams P;
    for (int i = 0; i < 9; i++) {
        P.w[i]   = (const float*)d_in[wi[i]];
        P.bia[i] = (const float*)d_in[wi[i]+1];
    }
    static const int pi[4] = {7,15,23,25};
    EpiParams E;
    for (int i = 0; i < 4; i++) {
        E.pw[i]    = (const float*)d_in[pi[i]];
        E.g[i]     = (const float*)d_in[pi[i]+1];
        E.gamma[i] = (const float*)d_in[27+i];
    }
    float* out = (float*)d_out;
    cudaFuncSetAttribute(cwam_mma, cudaFuncAttributeMaxDynamicSharedMemorySize, CWAM_SMEM);
    qkv_kernel <<<dim3(32,2),  256>>>(x, P);
    cam_kernel <<<dim3(2,8),   256>>>();
    pam_kernel <<<dim3(64,2),  256>>>();
    cham_kernel<<<dim3(128,2), 256>>>();
    cwam_mma   <<<dim3(96,2),  128, CWAM_SMEM>>>(x);
    epi_kernel <<<dim3(96,2),  256>>>(out, E);
}